// round 6
// baseline (speedup 1.0000x reference)
#include <cuda_runtime.h>
#include <math.h>
#include <stdint.h>

#define Bn  8
#define SQ  128
#define SK  128
#define IVD 32
#define DIM 32
#define EV  64
#define Hh  8
#define NH  128
#define DKd 8

// scratch (allocation-free rule: device globals)
__device__ float g_q[Bn*SQ*EV];
__device__ float g_k[Bn*SK*EV];
__device__ float g_w2q[NH*EV];     // w2 @ wq   [128,64]
__device__ float g_w2k[NH*EV];     // w2 @ wk   [128,64]
__device__ float g_woT[NH*Hh*DIM]; // wo^T      [128,256]

__device__ __forceinline__ void cp_async16(uint32_t saddr, const void* gaddr) {
    asm volatile("cp.async.cg.shared.global [%0], [%1], 16;\n"
                 :: "r"(saddr), "l"(gaddr));
}
__device__ __forceinline__ void cp_commit() {
    asm volatile("cp.async.commit_group;\n");
}
__device__ __forceinline__ void cp_wait0() {
    asm volatile("cp.async.wait_group 0;\n");
}

__device__ __forceinline__ float fast_tanh(float x) {
    x = fminf(fmaxf(x, -15.f), 15.f);
    float e = __expf(2.f * x);
    return __fdividef(e - 1.f, e + 1.f);
}

// ---------------------------------------------------------------------------
// K0 (208 blocks x 256 thr):
//   [0,32):   w2q = w2 @ wq   (4 i-rows/block)
//   [32,64):  w2k = w2 @ wk
//   [64,80):  woT transpose (2048 elems/block)
//   [80,208): impute MLP (8 rows/block)
// ---------------------------------------------------------------------------
__global__ void __launch_bounds__(256) prep_kernel(
    const float* __restrict__ w2,
    const float* __restrict__ wq, const float* __restrict__ wk,
    const float* __restrict__ wo,
    const float* __restrict__ imp,
    const float* __restrict__ wd1, const float* __restrict__ bd1,
    const float* __restrict__ lng, const float* __restrict__ lnb,
    const float* __restrict__ wd2, const float* __restrict__ bd2,
    float* __restrict__ qd_out)
{
    int t = threadIdx.x;
    int blk = blockIdx.x;

    if (blk < 64) {
        bool isQ = blk < 32;
        const float* w = isQ ? wq : wk;
        float* outp    = isQ ? g_w2q : g_w2k;
        int i = (isQ ? blk : blk - 32) * 4 + (t >> 6);
        int j = t & 63;
        float acc = 0.f;
        #pragma unroll 16
        for (int p = 0; p < EV; p++)
            acc = fmaf(w2[i*EV + p], w[p*EV + j], acc);
        outp[i*EV + j] = acc;
    } else if (blk < 80) {
        int base = (blk - 64) * 2048;
        #pragma unroll
        for (int jj = 0; jj < 8; jj++) {
            int e = base + t + jj*256;
            int c = e >> 8, p = e & 255;
            g_woT[e] = wo[p*NH + c];
        }
    } else {
        // impute MLP, 8 rows/block
        __shared__ __align__(16) float xi[128];
        __shared__ __align__(16) float htm[NH*8];
        __shared__ float redS[32], redQ[32];

        int row0 = (blk - 80) * 8;
        if (t < 128) xi[t] = imp[row0*16 + t];
        __syncthreads();

        int c1   = t & 127;
        int base = (t >> 7) * 4;
        int w8   = t >> 5;
        int lane = t & 31;

        float a[4];
        {
            float bb = bd1[c1];
            #pragma unroll
            for (int j = 0; j < 4; j++) a[j] = bb;
            #pragma unroll
            for (int i = 0; i < 16; i++) {
                float w = wd1[i*NH + c1];
                #pragma unroll
                for (int j = 0; j < 4; j++)
                    a[j] = fmaf(xi[(base+j)*16 + i], w, a[j]);
            }
        }
        float ss[4], qq[4];
        #pragma unroll
        for (int j = 0; j < 4; j++) { ss[j] = a[j]; qq[j] = a[j]*a[j]; }
        #pragma unroll
        for (int off = 16; off > 0; off >>= 1) {
            #pragma unroll
            for (int j = 0; j < 4; j++) {
                ss[j] += __shfl_xor_sync(0xffffffff, ss[j], off);
                qq[j] += __shfl_xor_sync(0xffffffff, qq[j], off);
            }
        }
        if (lane == 0) {
            #pragma unroll
            for (int j = 0; j < 4; j++) { redS[w8*4+j] = ss[j]; redQ[w8*4+j] = qq[j]; }
        }
        __syncthreads();

        float g = lng[c1], be = lnb[c1];
        int gw = (base == 0) ? 0 : 4;
        {
            float4 hv; float* hp = (float*)&hv;
            #pragma unroll
            for (int j = 0; j < 4; j++) {
                float S = redS[(gw+0)*4+j] + redS[(gw+1)*4+j]
                        + redS[(gw+2)*4+j] + redS[(gw+3)*4+j];
                float Q = redQ[(gw+0)*4+j] + redQ[(gw+1)*4+j]
                        + redQ[(gw+2)*4+j] + redQ[(gw+3)*4+j];
                float mu  = S * (1.f/128.f);
                float var = Q * (1.f/128.f) - mu*mu;
                float ln = (a[j] - mu) * rsqrtf(var + 1e-5f) * g + be;
                hp[j] = fmaxf(ln, 0.f);
            }
            *(float4*)&htm[c1*8 + base] = hv;
        }
        __syncthreads();

        float acc[4];
        {
            float bb = bd2[c1];
            #pragma unroll
            for (int j = 0; j < 4; j++) acc[j] = bb;
            #pragma unroll 8
            for (int p = 0; p < NH; p++) {
                float w = wd2[p*NH + c1];
                float4 h = *(const float4*)&htm[p*8 + base];
                acc[0] = fmaf(h.x, w, acc[0]);
                acc[1] = fmaf(h.y, w, acc[1]);
                acc[2] = fmaf(h.z, w, acc[2]);
                acc[3] = fmaf(h.w, w, acc[3]);
            }
        }
        #pragma unroll
        for (int j = 0; j < 4; j++)
            qd_out[(row0+base+j)*NH + c1] = acc[j];
    }
}

// ---------------------------------------------------------------------------
// K1 proj: 128 blocks x 256 thr, 16 rows/block.
//   h = tanh(X@w1+b1);  q/k = h @ w2{q,k} + b{q,k}   (K=128, folded weights)
// ---------------------------------------------------------------------------
__global__ void __launch_bounds__(256) proj_kernel(
    const float* __restrict__ qv, const float* __restrict__ kv,
    const float* __restrict__ w1, const float* __restrict__ b1,
    const float* __restrict__ bq, const float* __restrict__ bk)
{
    __shared__ __align__(16) float xs_t[IVD*16];    // [i][r] transposed, 2KB
    __shared__ __align__(16) float ht[NH*16];       // [p][r] transposed, 8KB
    __shared__ __align__(16) float ws[NH*EV];       // folded weights, 32KB

    int t = threadIdx.x;
    int r0 = blockIdx.x * 16;
    bool isQ = r0 < Bn*SQ;
    int rr0 = isQ ? r0 : r0 - Bn*SQ;
    const float* xin = isQ ? qv : kv;
    const float* wfold = isQ ? g_w2q : g_w2k;
    const float* bp  = isQ ? bq : bk;
    float* outp      = isQ ? g_q : g_k;

    // stage folded weights (latency hidden by phase 1)
    {
        uint32_t sb = (uint32_t)__cvta_generic_to_shared(ws);
        #pragma unroll
        for (int j = 0; j < 8; j++) {
            int idx = t + j*256;
            cp_async16(sb + idx*16, wfold + idx*4);
        }
        cp_commit();
    }

    #pragma unroll
    for (int j = 0; j < 2; j++) {
        int idx = t + j*256;
        int r = idx >> 5, i = idx & 31;
        xs_t[i*16 + r] = xin[rr0*IVD + idx];
    }
    __syncthreads();

    // phase 1: hidden
    {
        int c1  = t & 127;
        int rh1 = (t >> 7) * 8;
        float bb = b1[c1];
        float a[8];
        #pragma unroll
        for (int r = 0; r < 8; r++) a[r] = bb;
        #pragma unroll
        for (int i = 0; i < IVD; i++) {
            float w = w1[i*NH + c1];
            float4 x0 = *(const float4*)&xs_t[i*16 + rh1];
            float4 x1 = *(const float4*)&xs_t[i*16 + rh1 + 4];
            a[0] = fmaf(x0.x, w, a[0]);
            a[1] = fmaf(x0.y, w, a[1]);
            a[2] = fmaf(x0.z, w, a[2]);
            a[3] = fmaf(x0.w, w, a[3]);
            a[4] = fmaf(x1.x, w, a[4]);
            a[5] = fmaf(x1.y, w, a[5]);
            a[6] = fmaf(x1.z, w, a[6]);
            a[7] = fmaf(x1.w, w, a[7]);
        }
        float4 h0, h1;
        h0.x = fast_tanh(a[0]); h0.y = fast_tanh(a[1]);
        h0.z = fast_tanh(a[2]); h0.w = fast_tanh(a[3]);
        h1.x = fast_tanh(a[4]); h1.y = fast_tanh(a[5]);
        h1.z = fast_tanh(a[6]); h1.w = fast_tanh(a[7]);
        *(float4*)&ht[c1*16 + rh1]     = h0;
        *(float4*)&ht[c1*16 + rh1 + 4] = h1;
    }
    cp_wait0();
    __syncthreads();

    // phase 2: q/k = h @ ws + b   (K=128)
    {
        int c  = t & 63;
        int rg = (t >> 6) * 4;
        float bb = bp[c];
        float a0=bb, a1=bb, a2=bb, a3=bb;
        #pragma unroll 8
        for (int p = 0; p < NH; p++) {
            float w = ws[p*EV + c];
            float4 h = *(const float4*)&ht[p*16 + rg];
            a0 = fmaf(h.x, w, a0);
            a1 = fmaf(h.y, w, a1);
            a2 = fmaf(h.z, w, a2);
            a3 = fmaf(h.w, w, a3);
        }
        outp[(rr0+rg+0)*EV + c] = a0;
        outp[(rr0+rg+1)*EV + c] = a1;
        outp[(rr0+rg+2)*EV + c] = a2;
        outp[(rr0+rg+3)*EV + c] = a3;
    }
}

// ---------------------------------------------------------------------------
// K2 attn+out: 256 blocks x 256 thr. block = (b, 4-q tile), ALL 8 heads.
// smem (floats): ks[128*64] qs[4*64] mv[128*32] mf[128*32] es[32*128]
// epilogue: y = x @ wo + bo via woT (x stays in smem; overlays mv)
// ---------------------------------------------------------------------------
extern __shared__ float as[];
__global__ void __launch_bounds__(256) attn_kernel(
    const float* __restrict__ value, const int* __restrict__ mask,
    const float* __restrict__ bo, float* __restrict__ y_out)
{
    float* ks = as;              // 8192
    float* qs = as + 8192;       // 256
    float* mv = as + 8448;       // 4096
    float* mf = as + 12544;      // 4096
    float* es = as + 16640;      // 4096
    float* xs = mv;              // 1024 (overlay after phase B)

    int blk = blockIdx.x;
    int b   = blk >> 5;
    int q0  = (blk & 31) * 4;
    int t   = threadIdx.x;

    // loads
    {
        const float4* gk4 = (const float4*)g_k;
        float4* ks4 = (float4*)ks;
        #pragma unroll
        for (int j = 0; j < 8; j++) {
            int idx = t + j*256;               // 2048 float4s
            ks4[idx] = gk4[b*2048 + idx];
        }
        qs[t] = g_q[(b*SQ + q0 + (t>>6))*EV + (t&63)];
        const float4* v4 = (const float4*)(value + b*SK*DIM);
        const int4*   m4 = (const int4*)  (mask  + b*SK*DIM);
        float4* mv4 = (float4*)mv;
        float4* mf4 = (float4*)mf;
        #pragma unroll
        for (int j = 0; j < 4; j++) {
            int idx = t + j*256;               // 1024 float4s
            int4 mm = m4[idx]; float4 vv = v4[idx];
            float4 av, af;
            av.x = mm.x ? vv.x : 0.f;  af.x = mm.x ? 1.f : 0.f;
            av.y = mm.y ? vv.y : 0.f;  af.y = mm.y ? 1.f : 0.f;
            av.z = mm.z ? vv.z : 0.f;  af.z = mm.z ? 1.f : 0.f;
            av.w = mm.w ? vv.w : 0.f;  af.w = mm.w ? 1.f : 0.f;
            mv4[idx] = av; mf4[idx] = af;
        }
    }
    __syncthreads();

    const float scale = 0.35355339059327373f;   // 1/sqrt(8)

    // phase A: scores + softmax weights. vr=(q,h) 0..31, kq 0..7 (16 k each)
    {
        int vr = t >> 3;
        int q = vr >> 3, h = vr & 7;
        int kbase = (t & 7) * 16;
        float4 q0r = *(const float4*)&qs[q*EV + h*DKd];
        float4 q1r = *(const float4*)&qs[q*EV + h*DKd + 4];

        float s[16];
        #pragma unroll
        for (int i = 0; i < 16; i++) {
            const float4* kp = (const float4*)&ks[(kbase+i)*EV + h*DKd];
            float4 k0 = kp[0], k1 = kp[1];
            float acc = q0r.x*k0.x;
            acc = fmaf(q0r.y, k0.y, acc);
            acc = fmaf(q0r.z, k0.z, acc);
            acc = fmaf(q0r.w, k0.w, acc);
            acc = fmaf(q1r.x, k1.x, acc);
            acc = fmaf(q1r.y, k1.y, acc);
            acc = fmaf(q1r.z, k1.z, acc);
            acc = fmaf(q1r.w, k1.w, acc);
            s[i] = acc;
        }
        float mx = s[0];
        #pragma unroll
        for (int i = 1; i < 16; i++) mx = fmaxf(mx, s[i]);
        mx = fmaxf(mx, __shfl_xor_sync(0xffffffff, mx, 1));
        mx = fmaxf(mx, __shfl_xor_sync(0xffffffff, mx, 2));
        mx = fmaxf(mx, __shfl_xor_sync(0xffffffff, mx, 4));
        float msc = mx * scale;
        #pragma unroll
        for (int i = 0; i < 16; i++)
            es[vr*SK + kbase + i] = __expf(fmaf(s[i], scale, -msc));
    }
    __syncthreads();

    // phase B: num/den accumulate. vr 0..31, dq 0..7 (4 d each)
    float4 xo;
    int vrB = t >> 3, dqB = t & 7;
    {
        float n0=0.f, n1=0.f, n2=0.f, n3=0.f;
        float d0=0.f, d1=0.f, d2=0.f, d3=0.f;
        const float4* mv4 = (const float4*)mv;
        const float4* mf4 = (const float4*)mf;
        const float4* ep4 = (const float4*)&es[vrB*SK];
        #pragma unroll 4
        for (int k4 = 0; k4 < SK/4; k4++) {
            float4 e4 = ep4[k4];
            #pragma unroll
            for (int j = 0; j < 4; j++) {
                float e = (j==0) ? e4.x : (j==1) ? e4.y : (j==2) ? e4.z : e4.w;
                int k = k4*4 + j;
                float4 v = mv4[k*8 + dqB];
                float4 m = mf4[k*8 + dqB];
                n0 = fmaf(e, v.x, n0);  d0 = fmaf(e, m.x, d0);
                n1 = fmaf(e, v.y, n1);  d1 = fmaf(e, m.y, d1);
                n2 = fmaf(e, v.z, n2);  d2 = fmaf(e, m.z, d2);
                n3 = fmaf(e, v.w, n3);  d3 = fmaf(e, m.w, d3);
            }
        }
        xo.x = __fdividef(n0, d0); xo.y = __fdividef(n1, d1);
        xo.z = __fdividef(n2, d2); xo.w = __fdividef(n3, d3);
    }
    __syncthreads();    // all mv/mf reads done; safe to overlay xs
    {
        int q = vrB >> 3, h = vrB & 7;
        *(float4*)&xs[q*256 + h*DIM + dqB*4] = xo;
    }
    __syncthreads();

    // epilogue: y[q][c] = sum_p xs[q][p] * woT[c][p] + bo[c]
    {
        int c  = t & 127;
        int qg = (t >> 7) * 2;       // rows qg, qg+1
        float a0 = 0.f, a1 = 0.f;
        const float4* wt4 = (const float4*)&g_woT[c*256];
        const float4* x04 = (const float4*)&xs[qg*256];
        const float4* x14 = (const float4*)&xs[(qg+1)*256];
        #pragma unroll 8
        for (int p4 = 0; p4 < 64; p4++) {
            float4 w = wt4[p4];
            float4 xa = x04[p4];
            float4 xb = x14[p4];
            a0 = fmaf(xa.x, w.x, a0);  a1 = fmaf(xb.x, w.x, a1);
            a0 = fmaf(xa.y, w.y, a0);  a1 = fmaf(xb.y, w.y, a1);
            a0 = fmaf(xa.z, w.z, a0);  a1 = fmaf(xb.z, w.z, a1);
            a0 = fmaf(xa.w, w.w, a0);  a1 = fmaf(xb.w, w.w, a1);
        }
        float bb = bo[c];
        y_out[(b*SQ + q0 + qg  )*NH + c] = a0 + bb;
        y_out[(b*SQ + q0 + qg+1)*NH + c] = a1 + bb;
    }
}

// ---------------------------------------------------------------------------
extern "C" void kernel_launch(void* const* d_in, const int* in_sizes, int n_in,
                              void* d_out, int out_size)
{
    bool dictOrder = (in_sizes[4] == Bn*SK*DIM);

    const float *qv, *kv, *val, *imp, *w1, *b1, *w2, *wq, *bq, *wk, *bk,
                *wo, *bo, *wd1, *bd1, *lng, *lnb, *wd2, *bd2;
    const int* mask;

    if (dictOrder) {
        qv  = (const float*)d_in[0];  kv  = (const float*)d_in[1];
        val = (const float*)d_in[2];  imp = (const float*)d_in[3];
        mask= (const int*)  d_in[4];
        w1  = (const float*)d_in[5];  b1  = (const float*)d_in[6];
        w2  = (const float*)d_in[7];
        wq  = (const float*)d_in[8];  bq  = (const float*)d_in[9];
        wk  = (const float*)d_in[10]; bk  = (const float*)d_in[11];
        wo  = (const float*)d_in[12]; bo  = (const float*)d_in[13];
        wd1 = (const float*)d_in[14]; bd1 = (const float*)d_in[15];
        lng = (const float*)d_in[16]; lnb = (const float*)d_in[17];
        wd2 = (const float*)d_in[18]; bd2 = (const float*)d_in[19];
    } else {
        qv  = (const float*)d_in[0];  kv  = (const float*)d_in[1];
        val = (const float*)d_in[2];  imp = (const float*)d_in[3];
        w1  = (const float*)d_in[4];  b1  = (const float*)d_in[5];
        w2  = (const float*)d_in[6];
        wq  = (const float*)d_in[7];  bq  = (const float*)d_in[8];
        wk  = (const float*)d_in[9];  bk  = (const float*)d_in[10];
        wo  = (const float*)d_in[11]; bo  = (const float*)d_in[12];
        wd1 = (const float*)d_in[13]; bd1 = (const float*)d_in[14];
        lng = (const float*)d_in[15]; lnb = (const float*)d_in[16];
        wd2 = (const float*)d_in[17]; bd2 = (const float*)d_in[18];
        mask= (const int*)  d_in[19];
    }

    float* y  = (float*)d_out;                       // [8,128,128]
    float* qd = (float*)d_out + Bn*SQ*NH;            // [8,128,128]

    static bool attr_set = false;
    if (!attr_set) {
        cudaFuncSetAttribute(attn_kernel,
                             cudaFuncAttributeMaxDynamicSharedMemorySize,
                             20736 * sizeof(float));
        attr_set = true;
    }

    prep_kernel<<<208, 256>>>(w2, wq, wk, wo,
                              imp, wd1, bd1, lng, lnb, wd2, bd2, qd);
    proj_kernel<<<128, 256>>>(qv, kv, w1, b1, bq, bk);
    attn_kernel<<<256, 256, 20736 * sizeof(float)>>>(val, mask, bo, y);
}

// round 8
// speedup vs baseline: 1.9367x; 1.9367x over previous
#include <cuda_runtime.h>
#include <math.h>
#include <stdint.h>

#define Bn  8
#define SQ  128
#define SK  128
#define IVD 32
#define DIM 32
#define EV  64
#define Hh  8
#define NH  128
#define DKd 8

// scratch (allocation-free rule: device globals)
__device__ float g_q[Bn*SQ*EV];
__device__ float g_k[Bn*SK*EV];
__device__ unsigned long long g_bar = 0;   // monotonic ticket barrier

__device__ __forceinline__ void cp_async16(uint32_t saddr, const void* gaddr) {
    asm volatile("cp.async.cg.shared.global [%0], [%1], 16;\n"
                 :: "r"(saddr), "l"(gaddr));
}
__device__ __forceinline__ void cp_commit() {
    asm volatile("cp.async.commit_group;\n");
}
__device__ __forceinline__ void cp_wait0() {
    asm volatile("cp.async.wait_group 0;\n");
}

__device__ __forceinline__ float fast_tanh(float x) {
    x = fminf(fmaxf(x, -15.f), 15.f);
    float e = __expf(2.f * x);
    return __fdividef(e - 1.f, e + 1.f);
}

// ---------------------------------------------------------------------------
// Single fused kernel. 256 blocks x 256 threads, 81KB dyn smem (2 blocks/SM,
// all 256 co-resident -> grid barrier is deadlock-free).
//   Stage 1: proj, 8 rows/block of the 2048-row combined q/k set.
//   grid barrier (monotonic ticket counter; graph-replay safe)
//   Stage 2: attn block=(b, 4q, all 8 heads) + fused out-GEMM epilogue.
//   Tail:    impute MLP, 4 rows/block.
// ---------------------------------------------------------------------------
extern __shared__ float as[];
__global__ void __launch_bounds__(256) mega_kernel(
    const float* __restrict__ qv, const float* __restrict__ kv,
    const float* __restrict__ value, const int* __restrict__ mask,
    const float* __restrict__ w1, const float* __restrict__ b1,
    const float* __restrict__ w2,
    const float* __restrict__ wq, const float* __restrict__ bq,
    const float* __restrict__ wk, const float* __restrict__ bk,
    const float* __restrict__ wo, const float* __restrict__ bo,
    const float* __restrict__ imp,
    const float* __restrict__ wd1, const float* __restrict__ bd1,
    const float* __restrict__ lng, const float* __restrict__ lnb,
    const float* __restrict__ wd2, const float* __restrict__ bd2,
    float* __restrict__ y_out, float* __restrict__ qd_out)
{
    int t   = threadIdx.x;
    int blk = blockIdx.x;

    // ================= Stage 1: proj (8 rows/block) =================
    {
        float* xs_t = as;            // [i][r] 32x8 transposed, 256 f
        float* ht   = as + 256;      // [p][r] 128x8 transposed, 1024 f
        float* et   = as + 1280;     // [p][r] 64x8 transposed,  512 f
        float* ws2  = as + 1792;     // w2 staged, 8192 f

        int r0 = blk * 8;                      // row in [0,2048)
        bool isQ = r0 < Bn*SQ;
        int rr0 = isQ ? r0 : r0 - Bn*SQ;
        const float* xin = isQ ? qv : kv;
        const float* wp  = isQ ? wq : wk;
        const float* bp  = isQ ? bq : bk;
        float* outp      = isQ ? g_q : g_k;

        // stage w2 (latency hidden by phase 1)
        {
            uint32_t sb = (uint32_t)__cvta_generic_to_shared(ws2);
            #pragma unroll
            for (int j = 0; j < 8; j++) {
                int idx = t + j*256;           // 2048 float4s
                cp_async16(sb + idx*16, w2 + idx*4);
            }
            cp_commit();
        }

        // load 8 input rows transposed [i][r]
        {
            int r = t >> 5, i = t & 31;
            xs_t[i*8 + r] = xin[rr0*IVD + t];
        }
        __syncthreads();

        // phase 1: hidden. thread = (col c1 of 128, 4 rows)
        {
            int c1   = t & 127;
            int rh1  = (t >> 7) * 4;
            float bb = b1[c1];
            float a0=bb, a1=bb, a2=bb, a3=bb;
            #pragma unroll
            for (int i = 0; i < IVD; i++) {
                float w = w1[i*NH + c1];
                float4 x = *(const float4*)&xs_t[i*8 + rh1];
                a0 = fmaf(x.x, w, a0);
                a1 = fmaf(x.y, w, a1);
                a2 = fmaf(x.z, w, a2);
                a3 = fmaf(x.w, w, a3);
            }
            float4 h;
            h.x = fast_tanh(a0); h.y = fast_tanh(a1);
            h.z = fast_tanh(a2); h.w = fast_tanh(a3);
            *(float4*)&ht[c1*8 + rh1] = h;
        }
        cp_wait0();
        __syncthreads();

        int c  = t & 63;
        int rg = (t >> 6) * 2;        // rows rg, rg+1

        // phase 2: embed (all-smem)
        {
            float a0 = 0.f, a1 = 0.f;
            #pragma unroll 8
            for (int p = 0; p < NH; p++) {
                float w = ws2[p*EV + c];
                float2 h = *(const float2*)&ht[p*8 + rg];
                a0 = fmaf(h.x, w, a0);
                a1 = fmaf(h.y, w, a1);
            }
            float2 o; o.x = a0; o.y = a1;
            *(float2*)&et[c*8 + rg] = o;
        }
        __syncthreads();

        // phase 3: q/k projection
        {
            float bb = bp[c];
            float a0 = bb, a1 = bb;
            #pragma unroll 8
            for (int p = 0; p < EV; p++) {
                float w = wp[p*EV + c];
                float2 e = *(const float2*)&et[p*8 + rg];
                a0 = fmaf(e.x, w, a0);
                a1 = fmaf(e.y, w, a1);
            }
            outp[(rr0+rg+0)*EV + c] = a0;
            outp[(rr0+rg+1)*EV + c] = a1;
        }
    }

    // ================= grid barrier =================
    __threadfence();
    __syncthreads();
    if (t == 0) {
        unsigned long long ticket = atomicAdd(&g_bar, 1ULL);
        unsigned long long target = (ticket >> 8) * 256ULL + 256ULL;
        volatile unsigned long long* vb = &g_bar;
        while (*vb < target) { }
        __threadfence();
    }
    __syncthreads();

    // ================= Stage 2: attn + out epilogue =================
    float* ks = as;              // 8192
    float* qs = as + 8192;       // 256
    float* mv = as + 8448;       // 4096
    float* mf = as + 12544;      // 4096
    float* es = as + 16640;      // 4096
    float* xs = mv;              // 1024 overlay after phase B

    int b  = blk >> 5;
    int q0 = (blk & 31) * 4;

    // loads (g_q/g_k via L2 to dodge any stale-L1 risk across the barrier)
    {
        const float4* gk4 = (const float4*)g_k;
        float4* ks4 = (float4*)ks;
        #pragma unroll
        for (int j = 0; j < 8; j++) {
            int idx = t + j*256;               // 2048 float4s
            ks4[idx] = __ldcg(&gk4[b*2048 + idx]);
        }
        qs[t] = __ldcg(&g_q[(b*SQ + q0 + (t>>6))*EV + (t&63)]);
        const float4* v4 = (const float4*)(value + b*SK*DIM);
        const int4*   m4 = (const int4*)  (mask  + b*SK*DIM);
        float4* mv4 = (float4*)mv;
        float4* mf4 = (float4*)mf;
        #pragma unroll
        for (int j = 0; j < 4; j++) {
            int idx = t + j*256;               // 1024 float4s
            int4 mm = m4[idx]; float4 vv = v4[idx];
            float4 av, af;
            av.x = mm.x ? vv.x : 0.f;  af.x = mm.x ? 1.f : 0.f;
            av.y = mm.y ? vv.y : 0.f;  af.y = mm.y ? 1.f : 0.f;
            av.z = mm.z ? vv.z : 0.f;  af.z = mm.z ? 1.f : 0.f;
            av.w = mm.w ? vv.w : 0.f;  af.w = mm.w ? 1.f : 0.f;
            mv4[idx] = av; mf4[idx] = af;
        }
    }
    __syncthreads();

    const float scale = 0.35355339059327373f;   // 1/sqrt(8)

    // phase A: scores + softmax weights. vr=(q,h) 0..31, kq 0..7 (16 k each)
    {
        int vr = t >> 3;
        int q = vr >> 3, h = vr & 7;
        int kbase = (t & 7) * 16;
        float4 q0r = *(const float4*)&qs[q*EV + h*DKd];
        float4 q1r = *(const float4*)&qs[q*EV + h*DKd + 4];

        float s[16];
        #pragma unroll
        for (int i = 0; i < 16; i++) {
            const float4* kp = (const float4*)&ks[(kbase+i)*EV + h*DKd];
            float4 k0 = kp[0], k1 = kp[1];
            float acc = q0r.x*k0.x;
            acc = fmaf(q0r.y, k0.y, acc);
            acc = fmaf(q0r.z, k0.z, acc);
            acc = fmaf(q0r.w, k0.w, acc);
            acc = fmaf(q1r.x, k1.x, acc);
            acc = fmaf(q1r.y, k1.y, acc);
            acc = fmaf(q1r.z, k1.z, acc);
            acc = fmaf(q1r.w, k1.w, acc);
            s[i] = acc;
        }
        float mx = s[0];
        #pragma unroll
        for (int i = 1; i < 16; i++) mx = fmaxf(mx, s[i]);
        mx = fmaxf(mx, __shfl_xor_sync(0xffffffff, mx, 1));
        mx = fmaxf(mx, __shfl_xor_sync(0xffffffff, mx, 2));
        mx = fmaxf(mx, __shfl_xor_sync(0xffffffff, mx, 4));
        float msc = mx * scale;
        #pragma unroll
        for (int i = 0; i < 16; i++)
            es[vr*SK + kbase + i] = __expf(fmaf(s[i], scale, -msc));
    }
    __syncthreads();

    // phase B: num/den accumulate. vr 0..31, dq 0..7 (4 d each)
    float4 xo;
    int vrB = t >> 3, dqB = t & 7;
    {
        float n0=0.f, n1=0.f, n2=0.f, n3=0.f;
        float d0=0.f, d1=0.f, d2=0.f, d3=0.f;
        const float4* mv4 = (const float4*)mv;
        const float4* mf4 = (const float4*)mf;
        const float4* ep4 = (const float4*)&es[vrB*SK];
        #pragma unroll 4
        for (int k4 = 0; k4 < SK/4; k4++) {
            float4 e4 = ep4[k4];
            #pragma unroll
            for (int j = 0; j < 4; j++) {
                float e = (j==0) ? e4.x : (j==1) ? e4.y : (j==2) ? e4.z : e4.w;
                int k = k4*4 + j;
                float4 v = mv4[k*8 + dqB];
                float4 m = mf4[k*8 + dqB];
                n0 = fmaf(e, v.x, n0);  d0 = fmaf(e, m.x, d0);
                n1 = fmaf(e, v.y, n1);  d1 = fmaf(e, m.y, d1);
                n2 = fmaf(e, v.z, n2);  d2 = fmaf(e, m.z, d2);
                n3 = fmaf(e, v.w, n3);  d3 = fmaf(e, m.w, d3);
            }
        }
        xo.x = __fdividef(n0, d0); xo.y = __fdividef(n1, d1);
        xo.z = __fdividef(n2, d2); xo.w = __fdividef(n3, d3);
    }
    __syncthreads();    // mv/mf reads done; safe to overlay xs
    {
        int q = vrB >> 3, h = vrB & 7;
        *(float4*)&xs[q*256 + h*DIM + dqB*4] = xo;
    }
    __syncthreads();

    // epilogue: y[q][c] = sum_p xs[q][p] * wo[p][c] + bo[c]
    // wo read in natural layout -> coalesced broadcast across the block.
    {
        int c    = t & 127;
        int half = t >> 7;            // rows half*2, half*2+1
        int qg   = half * 2;
        float a0 = 0.f, a1 = 0.f;
        const float* x0p = &xs[qg*256];
        const float* x1p = &xs[(qg+1)*256];
        #pragma unroll 8
        for (int p = 0; p < 256; p++) {
            float w = wo[p*NH + c];
            a0 = fmaf(x0p[p], w, a0);
            a1 = fmaf(x1p[p], w, a1);
        }
        float bb = bo[c];
        y_out[(b*SQ + q0 + qg  )*NH + c] = a0 + bb;
        y_out[(b*SQ + q0 + qg+1)*NH + c] = a1 + bb;
    }

    // ================= Tail: impute MLP (4 rows/block) =================
    {
        float* xi   = es;          // 64 f (es reads finished before epilogue)
        float* htm  = es + 64;     // [128][4] transposed, 512 f
        float* redS = es + 576;    // 16 f
        float* redQ = es + 592;    // 16 f

        int row0 = blk * 4;
        __syncthreads();
        if (t < 64) xi[t] = imp[row0*16 + t];
        __syncthreads();

        int c1   = t & 127;
        int half = t >> 7;         // rows half*2 + {0,1}
        int w8   = t >> 5;
        int lane = t & 31;

        float a[2];
        {
            float bb = bd1[c1];
            a[0] = bb; a[1] = bb;
            #pragma unroll
            for (int i = 0; i < 16; i++) {
                float w = wd1[i*NH + c1];
                a[0] = fmaf(xi[(half*2+0)*16 + i], w, a[0]);
                a[1] = fmaf(xi[(half*2+1)*16 + i], w, a[1]);
            }
        }
        float ss0 = a[0], ss1 = a[1];
        float qq0 = a[0]*a[0], qq1 = a[1]*a[1];
        #pragma unroll
        for (int off = 16; off > 0; off >>= 1) {
            ss0 += __shfl_xor_sync(0xffffffff, ss0, off);
            ss1 += __shfl_xor_sync(0xffffffff, ss1, off);
            qq0 += __shfl_xor_sync(0xffffffff, qq0, off);
            qq1 += __shfl_xor_sync(0xffffffff, qq1, off);
        }
        if (lane == 0) {
            redS[w8*2+0] = ss0; redS[w8*2+1] = ss1;
            redQ[w8*2+0] = qq0; redQ[w8*2+1] = qq1;
        }
        __syncthreads();

        {
            float g = lng[c1], be = lnb[c1];
            int wb = half * 4;     // warps wb..wb+3 hold this half's rows
            float2 hv;
            float* hp = (float*)&hv;
            #pragma unroll
            for (int j = 0; j < 2; j++) {
                float S = redS[(wb+0)*2+j] + redS[(wb+1)*2+j]
                        + redS[(wb+2)*2+j] + redS[(wb+3)*2+j];
                float Q = redQ[(wb+0)*2+j] + redQ[(wb+1)*2+j]
                        + redQ[(wb+2)*2+j] + redQ[(wb+3)*2+j];
                float mu  = S * (1.f/128.f);
                float var = Q * (1.f/128.f) - mu*mu;
                float ln = (a[j] - mu) * rsqrtf(var + 1e-5f) * g + be;
                hp[j] = fmaxf(ln, 0.f);
            }
            *(float2*)&htm[c1*4 + half*2] = hv;
        }
        __syncthreads();

        {
            float bb = bd2[c1];
            float a0 = bb, a1 = bb;
            #pragma unroll 8
            for (int p = 0; p < NH; p++) {
                float w = wd2[p*NH + c1];
                float2 h = *(const float2*)&htm[p*4 + half*2];
                a0 = fmaf(h.x, w, a0);
                a1 = fmaf(h.y, w, a1);
            }
            qd_out[(row0 + half*2 + 0)*NH + c1] = a0;
            qd_out[(row0 + half*2 + 1)*NH + c1] = a1;
        }
    }
}

// ---------------------------------------------------------------------------
extern "C" void kernel_launch(void* const* d_in, const int* in_sizes, int n_in,
                              void* d_out, int out_size)
{
    bool dictOrder = (in_sizes[4] == Bn*SK*DIM);

    const float *qv, *kv, *val, *imp, *w1, *b1, *w2, *wq, *bq, *wk, *bk,
                *wo, *bo, *wd1, *bd1, *lng, *lnb, *wd2, *bd2;
    const int* mask;

    if (dictOrder) {
        qv  = (const float*)d_in[0];  kv  = (const float*)d_in[1];
        val = (const float*)d_in[2];  imp = (const float*)d_in[3];
        mask= (const int*)  d_in[4];
        w1  = (const float*)d_in[5];  b1  = (const float*)d_in[6];
        w2  = (const float*)d_in[7];
        wq  = (const float*)d_in[8];  bq  = (const float*)d_in[9];
        wk  = (const float*)d_in[10]; bk  = (const float*)d_in[11];
        wo  = (const float*)d_in[12]; bo  = (const float*)d_in[13];
        wd1 = (const float*)d_in[14]; bd1 = (const float*)d_in[15];
        lng = (const float*)d_in[16]; lnb = (const float*)d_in[17];
        wd2 = (const float*)d_in[18]; bd2 = (const float*)d_in[19];
    } else {
        qv  = (const float*)d_in[0];  kv  = (const float*)d_in[1];
        val = (const float*)d_in[2];  imp = (const float*)d_in[3];
        w1  = (const float*)d_in[4];  b1  = (const float*)d_in[5];
        w2  = (const float*)d_in[6];
        wq  = (const float*)d_in[7];  bq  = (const float*)d_in[8];
        wk  = (const float*)d_in[9];  bk  = (const float*)d_in[10];
        wo  = (const float*)d_in[11]; bo  = (const float*)d_in[12];
        wd1 = (const float*)d_in[13]; bd1 = (const float*)d_in[14];
        lng = (const float*)d_in[15]; lnb = (const float*)d_in[16];
        wd2 = (const float*)d_in[17]; bd2 = (const float*)d_in[18];
        mask= (const int*)  d_in[19];
    }

    float* y  = (float*)d_out;                       // [8,128,128]
    float* qd = (float*)d_out + Bn*SQ*NH;            // [8,128,128]

    cudaFuncSetAttribute(mega_kernel,
                         cudaFuncAttributeMaxDynamicSharedMemorySize,
                         20736 * sizeof(float));

    mega_kernel<<<256, 256, 20736 * sizeof(float)>>>(
        qv, kv, val, mask, w1, b1, w2, wq, bq, wk, bk, wo, bo,
        imp, wd1, bd1, lng, lnb, wd2, bd2, y, qd);
}

// round 9
// speedup vs baseline: 2.1364x; 1.1031x over previous
#include <cuda_runtime.h>
#include <math.h>
#include <stdint.h>

#define Bn  8
#define SQ  128
#define SK  128
#define IVD 32
#define DIM 32
#define EV  64
#define Hh  8
#define NH  128
#define DKd 8

// scratch (allocation-free rule: device globals)
__device__ float g_q[Bn*SQ*EV];
__device__ float g_k[Bn*SK*EV];
__device__ unsigned long long g_bar = 0;   // monotonic ticket barrier

__device__ __forceinline__ void cp_async16(uint32_t saddr, const void* gaddr) {
    asm volatile("cp.async.cg.shared.global [%0], [%1], 16;\n"
                 :: "r"(saddr), "l"(gaddr));
}
__device__ __forceinline__ void cp_commit() {
    asm volatile("cp.async.commit_group;\n");
}
__device__ __forceinline__ void cp_wait0() {
    asm volatile("cp.async.wait_group 0;\n");
}

__device__ __forceinline__ float fast_tanh(float x) {
    x = fminf(fmaxf(x, -15.f), 15.f);
    float e = __expf(2.f * x);
    return __fdividef(e - 1.f, e + 1.f);
}

// ---------------------------------------------------------------------------
// Single fused kernel. 256 blocks x 256 threads, 81KB dyn smem (2 blocks/SM,
// all 256 co-resident -> grid barrier deadlock-free).
//   Stage 1: blocks [0,128)   : proj, 16 rows/block (R5 shape, best measured)
//            blocks [128,256) : impute MLP, 8 rows/block (independent branch)
//   grid barrier (monotonic ticket, nanosleep backoff)
//   Stage 2: all blocks: attn block=(b, 4q, 8 heads) + fused out-GEMM.
// ---------------------------------------------------------------------------
extern __shared__ float as[];
__global__ void __launch_bounds__(256) mega_kernel(
    const float* __restrict__ qv, const float* __restrict__ kv,
    const float* __restrict__ value, const int* __restrict__ mask,
    const float* __restrict__ w1, const float* __restrict__ b1,
    const float* __restrict__ w2,
    const float* __restrict__ wq, const float* __restrict__ bq,
    const float* __restrict__ wk, const float* __restrict__ bk,
    const float* __restrict__ wo, const float* __restrict__ bo,
    const float* __restrict__ imp,
    const float* __restrict__ wd1, const float* __restrict__ bd1,
    const float* __restrict__ lng, const float* __restrict__ lnb,
    const float* __restrict__ wd2, const float* __restrict__ bd2,
    float* __restrict__ y_out, float* __restrict__ qd_out)
{
    int t   = threadIdx.x;
    int blk = blockIdx.x;

    if (blk < 128) {
        // ========== Stage 1a: proj, 16 rows/block ==========
        float* xs_t = as;            // [i][r] 32x16 transposed, 512 f
        float* ht   = as + 512;      // [p][r] 128x16 transposed, 2048 f
        float* et   = as + 2560;     // [p][r] 64x16 transposed, 1024 f
        float* ws2  = as + 3584;     // 8192 f

        int r0 = blk * 16;                     // row in [0,2048)
        bool isQ = r0 < Bn*SQ;
        int rr0 = isQ ? r0 : r0 - Bn*SQ;
        const float* xin = isQ ? qv : kv;
        const float* wp  = isQ ? wq : wk;
        const float* bp  = isQ ? bq : bk;
        float* outp      = isQ ? g_q : g_k;

        // stage w2 (latency hidden by phase 1)
        {
            uint32_t sb = (uint32_t)__cvta_generic_to_shared(ws2);
            #pragma unroll
            for (int j = 0; j < 8; j++) {
                int idx = t + j*256;           // 2048 float4s
                cp_async16(sb + idx*16, w2 + idx*4);
            }
            cp_commit();
        }

        // load 16 input rows, transposed [i][r]
        #pragma unroll
        for (int j = 0; j < 2; j++) {
            int idx = t + j*256;               // 0..511
            int r = idx >> 5, i = idx & 31;
            xs_t[i*16 + r] = xin[rr0*IVD + idx];
        }
        __syncthreads();

        // phase 1: hidden. thread = (col c1 of 128, 8 rows)
        {
            int c1  = t & 127;
            int rh1 = (t >> 7) * 8;
            float bb = b1[c1];
            float a[8];
            #pragma unroll
            for (int r = 0; r < 8; r++) a[r] = bb;
            #pragma unroll
            for (int i = 0; i < IVD; i++) {
                float w = w1[i*NH + c1];
                float4 x0 = *(const float4*)&xs_t[i*16 + rh1];
                float4 x1 = *(const float4*)&xs_t[i*16 + rh1 + 4];
                a[0] = fmaf(x0.x, w, a[0]);
                a[1] = fmaf(x0.y, w, a[1]);
                a[2] = fmaf(x0.z, w, a[2]);
                a[3] = fmaf(x0.w, w, a[3]);
                a[4] = fmaf(x1.x, w, a[4]);
                a[5] = fmaf(x1.y, w, a[5]);
                a[6] = fmaf(x1.z, w, a[6]);
                a[7] = fmaf(x1.w, w, a[7]);
            }
            float4 h0, h1;
            h0.x = fast_tanh(a[0]); h0.y = fast_tanh(a[1]);
            h0.z = fast_tanh(a[2]); h0.w = fast_tanh(a[3]);
            h1.x = fast_tanh(a[4]); h1.y = fast_tanh(a[5]);
            h1.z = fast_tanh(a[6]); h1.w = fast_tanh(a[7]);
            *(float4*)&ht[c1*16 + rh1]     = h0;
            *(float4*)&ht[c1*16 + rh1 + 4] = h1;
        }
        cp_wait0();
        __syncthreads();

        int c  = t & 63;
        int rg = (t >> 6) * 4;        // rows rg..rg+3

        // phase 2: embed (all-smem)
        {
            float a0=0.f, a1=0.f, a2=0.f, a3=0.f;
            #pragma unroll 8
            for (int p = 0; p < NH; p++) {
                float w = ws2[p*EV + c];
                float4 h = *(const float4*)&ht[p*16 + rg];
                a0 = fmaf(h.x, w, a0);
                a1 = fmaf(h.y, w, a1);
                a2 = fmaf(h.z, w, a2);
                a3 = fmaf(h.w, w, a3);
            }
            float4 o; o.x=a0; o.y=a1; o.z=a2; o.w=a3;
            *(float4*)&et[c*16 + rg] = o;
        }
        __syncthreads();

        // phase 3: q/k projection
        {
            float bb = bp[c];
            float a0=bb, a1=bb, a2=bb, a3=bb;
            #pragma unroll 8
            for (int p = 0; p < EV; p++) {
                float w = wp[p*EV + c];
                float4 e = *(const float4*)&et[p*16 + rg];
                a0 = fmaf(e.x, w, a0);
                a1 = fmaf(e.y, w, a1);
                a2 = fmaf(e.z, w, a2);
                a3 = fmaf(e.w, w, a3);
            }
            outp[(rr0+rg+0)*EV + c] = a0;
            outp[(rr0+rg+1)*EV + c] = a1;
            outp[(rr0+rg+2)*EV + c] = a2;
            outp[(rr0+rg+3)*EV + c] = a3;
        }
    } else {
        // ========== Stage 1b: impute MLP, 8 rows/block ==========
        float* xi   = as;            // [8][16] 128 f
        float* htm  = as + 128;      // [128][8] transposed, 1024 f
        float* redS = as + 1152;     // 32 f
        float* redQ = as + 1184;     // 32 f

        int row0 = (blk - 128) * 8;
        if (t < 128) xi[t] = imp[row0*16 + t];
        __syncthreads();

        int c1   = t & 127;
        int base = (t >> 7) * 4;     // rows base..base+3
        int w8   = t >> 5;
        int lane = t & 31;

        float a[4];
        {
            float bb = bd1[c1];
            #pragma unroll
            for (int j = 0; j < 4; j++) a[j] = bb;
            #pragma unroll
            for (int i = 0; i < 16; i++) {
                float w = wd1[i*NH + c1];
                #pragma unroll
                for (int j = 0; j < 4; j++)
                    a[j] = fmaf(xi[(base+j)*16 + i], w, a[j]);
            }
        }
        float ss[4], qq[4];
        #pragma unroll
        for (int j = 0; j < 4; j++) { ss[j] = a[j]; qq[j] = a[j]*a[j]; }
        #pragma unroll
        for (int off = 16; off > 0; off >>= 1) {
            #pragma unroll
            for (int j = 0; j < 4; j++) {
                ss[j] += __shfl_xor_sync(0xffffffff, ss[j], off);
                qq[j] += __shfl_xor_sync(0xffffffff, qq[j], off);
            }
        }
        if (lane == 0) {
            #pragma unroll
            for (int j = 0; j < 4; j++) { redS[w8*4+j] = ss[j]; redQ[w8*4+j] = qq[j]; }
        }
        __syncthreads();

        float g = lng[c1], be = lnb[c1];
        int gw = (base == 0) ? 0 : 4;
        {
            float4 hv; float* hp = (float*)&hv;
            #pragma unroll
            for (int j = 0; j < 4; j++) {
                float S = redS[(gw+0)*4+j] + redS[(gw+1)*4+j]
                        + redS[(gw+2)*4+j] + redS[(gw+3)*4+j];
                float Q = redQ[(gw+0)*4+j] + redQ[(gw+1)*4+j]
                        + redQ[(gw+2)*4+j] + redQ[(gw+3)*4+j];
                float mu  = S * (1.f/128.f);
                float var = Q * (1.f/128.f) - mu*mu;
                float ln = (a[j] - mu) * rsqrtf(var + 1e-5f) * g + be;
                hp[j] = fmaxf(ln, 0.f);
            }
            *(float4*)&htm[c1*8 + base] = hv;
        }
        __syncthreads();

        float acc[4];
        {
            float bb = bd2[c1];
            #pragma unroll
            for (int j = 0; j < 4; j++) acc[j] = bb;
            #pragma unroll 8
            for (int p = 0; p < NH; p++) {
                float w = wd2[p*NH + c1];
                float4 h = *(const float4*)&htm[p*8 + base];
                acc[0] = fmaf(h.x, w, acc[0]);
                acc[1] = fmaf(h.y, w, acc[1]);
                acc[2] = fmaf(h.z, w, acc[2]);
                acc[3] = fmaf(h.w, w, acc[3]);
            }
        }
        #pragma unroll
        for (int j = 0; j < 4; j++)
            qd_out[(row0+base+j)*NH + c1] = acc[j];
    }

    // ================= grid barrier =================
    __threadfence();
    __syncthreads();
    if (t == 0) {
        unsigned long long ticket = atomicAdd(&g_bar, 1ULL);
        unsigned long long target = (ticket >> 8) * 256ULL + 256ULL;
        volatile unsigned long long* vb = &g_bar;
        while (*vb < target) { __nanosleep(64); }
        __threadfence();
    }
    __syncthreads();

    // ================= Stage 2: attn + out epilogue =================
    float* ks = as;              // 8192
    float* qs = as + 8192;       // 256
    float* mv = as + 8448;       // 4096
    float* mf = as + 12544;      // 4096
    float* es = as + 16640;      // 4096
    float* xs = mv;              // 1024 overlay after phase B

    int b  = blk >> 5;
    int q0 = (blk & 31) * 4;

    // loads (g_q/g_k via L2 to dodge stale-L1 risk across the barrier)
    {
        const float4* gk4 = (const float4*)g_k;
        float4* ks4 = (float4*)ks;
        #pragma unroll
        for (int j = 0; j < 8; j++) {
            int idx = t + j*256;               // 2048 float4s
            ks4[idx] = __ldcg(&gk4[b*2048 + idx]);
        }
        qs[t] = __ldcg(&g_q[(b*SQ + q0 + (t>>6))*EV + (t&63)]);
        const float4* v4 = (const float4*)(value + b*SK*DIM);
        const int4*   m4 = (const int4*)  (mask  + b*SK*DIM);
        float4* mv4 = (float4*)mv;
        float4* mf4 = (float4*)mf;
        #pragma unroll
        for (int j = 0; j < 4; j++) {
            int idx = t + j*256;               // 1024 float4s
            int4 mm = m4[idx]; float4 vv = v4[idx];
            float4 av, af;
            av.x = mm.x ? vv.x : 0.f;  af.x = mm.x ? 1.f : 0.f;
            av.y = mm.y ? vv.y : 0.f;  af.y = mm.y ? 1.f : 0.f;
            av.z = mm.z ? vv.z : 0.f;  af.z = mm.z ? 1.f : 0.f;
            av.w = mm.w ? vv.w : 0.f;  af.w = mm.w ? 1.f : 0.f;
            mv4[idx] = av; mf4[idx] = af;
        }
    }
    __syncthreads();

    const float scale = 0.35355339059327373f;   // 1/sqrt(8)

    // phase A: scores + softmax weights. vr=(q,h) 0..31, kq 0..7 (16 k each)
    {
        int vr = t >> 3;
        int q = vr >> 3, h = vr & 7;
        int kbase = (t & 7) * 16;
        float4 q0r = *(const float4*)&qs[q*EV + h*DKd];
        float4 q1r = *(const float4*)&qs[q*EV + h*DKd + 4];

        float s[16];
        #pragma unroll
        for (int i = 0; i < 16; i++) {
            const float4* kp = (const float4*)&ks[(kbase+i)*EV + h*DKd];
            float4 k0 = kp[0], k1 = kp[1];
            float acc = q0r.x*k0.x;
            acc = fmaf(q0r.y, k0.y, acc);
            acc = fmaf(q0r.z, k0.z, acc);
            acc = fmaf(q0r.w, k0.w, acc);
            acc = fmaf(q1r.x, k1.x, acc);
            acc = fmaf(q1r.y, k1.y, acc);
            acc = fmaf(q1r.z, k1.z, acc);
            acc = fmaf(q1r.w, k1.w, acc);
            s[i] = acc;
        }
        float mx = s[0];
        #pragma unroll
        for (int i = 1; i < 16; i++) mx = fmaxf(mx, s[i]);
        mx = fmaxf(mx, __shfl_xor_sync(0xffffffff, mx, 1));
        mx = fmaxf(mx, __shfl_xor_sync(0xffffffff, mx, 2));
        mx = fmaxf(mx, __shfl_xor_sync(0xffffffff, mx, 4));
        float msc = mx * scale;
        #pragma unroll
        for (int i = 0; i < 16; i++)
            es[vr*SK + kbase + i] = __expf(fmaf(s[i], scale, -msc));
    }
    __syncthreads();

    // phase B: num/den accumulate. vr 0..31, dq 0..7 (4 d each)
    float4 xo;
    int vrB = t >> 3, dqB = t & 7;
    {
        float n0=0.f, n1=0.f, n2=0.f, n3=0.f;
        float d0=0.f, d1=0.f, d2=0.f, d3=0.f;
        const float4* mv4 = (const float4*)mv;
        const float4* mf4 = (const float4*)mf;
        const float4* ep4 = (const float4*)&es[vrB*SK];
        #pragma unroll 4
        for (int k4 = 0; k4 < SK/4; k4++) {
            float4 e4 = ep4[k4];
            #pragma unroll
            for (int j = 0; j < 4; j++) {
                float e = (j==0) ? e4.x : (j==1) ? e4.y : (j==2) ? e4.z : e4.w;
                int k = k4*4 + j;
                float4 v = mv4[k*8 + dqB];
                float4 m = mf4[k*8 + dqB];
                n0 = fmaf(e, v.x, n0);  d0 = fmaf(e, m.x, d0);
                n1 = fmaf(e, v.y, n1);  d1 = fmaf(e, m.y, d1);
                n2 = fmaf(e, v.z, n2);  d2 = fmaf(e, m.z, d2);
                n3 = fmaf(e, v.w, n3);  d3 = fmaf(e, m.w, d3);
            }
        }
        xo.x = __fdividef(n0, d0); xo.y = __fdividef(n1, d1);
        xo.z = __fdividef(n2, d2); xo.w = __fdividef(n3, d3);
    }
    __syncthreads();    // mv/mf reads done; safe to overlay xs
    {
        int q = vrB >> 3, h = vrB & 7;
        *(float4*)&xs[q*256 + h*DIM + dqB*4] = xo;
    }
    __syncthreads();

    // epilogue: y[q][c] = sum_p xs[q][p] * wo[p][c] + bo[c]  (coalesced wo)
    {
        int c    = t & 127;
        int qg   = (t >> 7) * 2;      // rows qg, qg+1
        float a0 = 0.f, a1 = 0.f;
        const float* x0p = &xs[qg*256];
        const float* x1p = &xs[(qg+1)*256];
        #pragma unroll 8
        for (int p = 0; p < 256; p++) {
            float w = wo[p*NH + c];
            a0 = fmaf(x0p[p], w, a0);
            a1 = fmaf(x1p[p], w, a1);
        }
        float bb = bo[c];
        y_out[(b*SQ + q0 + qg  )*NH + c] = a0 + bb;
        y_out[(b*SQ + q0 + qg+1)*NH + c] = a1 + bb;
    }
}

// ---------------------------------------------------------------------------
extern "C" void kernel_launch(void* const* d_in, const int* in_sizes, int n_in,
                              void* d_out, int out_size)
{
    bool dictOrder = (in_sizes[4] == Bn*SK*DIM);

    const float *qv, *kv, *val, *imp, *w1, *b1, *w2, *wq, *bq, *wk, *bk,
                *wo, *bo, *wd1, *bd1, *lng, *lnb, *wd2, *bd2;
    const int* mask;

    if (dictOrder) {
        qv  = (const float*)d_in[0];  kv  = (const float*)d_in[1];
        val = (const float*)d_in[2];  imp = (const float*)d_in[3];
        mask= (const int*)  d_in[4];
        w1  = (const float*)d_in[5];  b1  = (const float*)d_in[6];
        w2  = (const float*)d_in[7];
        wq  = (const float*)d_in[8];  bq  = (const float*)d_in[9];
        wk  = (const float*)d_in[10]; bk  = (const float*)d_in[11];
        wo  = (const float*)d_in[12]; bo  = (const float*)d_in[13];
        wd1 = (const float*)d_in[14]; bd1 = (const float*)d_in[15];
        lng = (const float*)d_in[16]; lnb = (const float*)d_in[17];
        wd2 = (const float*)d_in[18]; bd2 = (const float*)d_in[19];
    } else {
        qv  = (const float*)d_in[0];  kv  = (const float*)d_in[1];
        val = (const float*)d_in[2];  imp = (const float*)d_in[3];
        w1  = (const float*)d_in[4];  b1  = (const float*)d_in[5];
        w2  = (const float*)d_in[6];
        wq  = (const float*)d_in[7];  bq  = (const float*)d_in[8];
        wk  = (const float*)d_in[9];  bk  = (const float*)d_in[10];
        wo  = (const float*)d_in[11]; bo  = (const float*)d_in[12];
        wd1 = (const float*)d_in[13]; bd1 = (const float*)d_in[14];
        lng = (const float*)d_in[15]; lnb = (const float*)d_in[16];
        wd2 = (const float*)d_in[17]; bd2 = (const float*)d_in[18];
        mask= (const int*)  d_in[19];
    }

    float* y  = (float*)d_out;                       // [8,128,128]
    float* qd = (float*)d_out + Bn*SQ*NH;            // [8,128,128]

    cudaFuncSetAttribute(mega_kernel,
                         cudaFuncAttributeMaxDynamicSharedMemorySize,
                         20736 * sizeof(float));

    mega_kernel<<<256, 256, 20736 * sizeof(float)>>>(
        qv, kv, val, mask, w1, b1, w2, wq, bq, wk, bk, wo, bo,
        imp, wd1, bd1, lng, lnb, wd2, bd2, y, qd);
}

// round 10
// speedup vs baseline: 2.1381x; 1.0008x over previous
#include <cuda_runtime.h>
#include <math.h>
#include <stdint.h>

#define Bn  8
#define SQ  128
#define SK  128
#define IVD 32
#define DIM 32
#define EV  64
#define Hh  8
#define NH  128
#define DKd 8

typedef unsigned long long u64;

// scratch (allocation-free rule: device globals)
__device__ float g_q[Bn*SQ*EV];
__device__ float g_k[Bn*SK*EV];
__device__ unsigned long long g_bar = 0;   // monotonic ticket barrier

__device__ __forceinline__ void cp_async16(uint32_t saddr, const void* gaddr) {
    asm volatile("cp.async.cg.shared.global [%0], [%1], 16;\n"
                 :: "r"(saddr), "l"(gaddr));
}
__device__ __forceinline__ void cp_commit() {
    asm volatile("cp.async.commit_group;\n");
}
__device__ __forceinline__ void cp_wait0() {
    asm volatile("cp.async.wait_group 0;\n");
}

__device__ __forceinline__ float fast_tanh(float x) {
    x = fminf(fmaxf(x, -15.f), 15.f);
    float e = __expf(2.f * x);
    return __fdividef(e - 1.f, e + 1.f);
}

// ---- packed fp32x2 (Blackwell FFMA2; per-lane IEEE fp32) ----
__device__ __forceinline__ u64 pack2(float lo, float hi) {
    u64 r; asm("mov.b64 %0, {%1, %2};" : "=l"(r) : "f"(lo), "f"(hi)); return r;
}
__device__ __forceinline__ void unpack2(u64 v, float& lo, float& hi) {
    asm("mov.b64 {%0, %1}, %2;" : "=f"(lo), "=f"(hi) : "l"(v));
}
__device__ __forceinline__ u64 fma2(u64 a, u64 b, u64 c) {
    u64 d; asm("fma.rn.f32x2 %0, %1, %2, %3;"
               : "=l"(d) : "l"(a), "l"(b), "l"(c)); return d;
}

// ---------------------------------------------------------------------------
// Single fused kernel. 256 blocks x 256 threads, 81KB dyn smem (2 blocks/SM
// capacity -> all 256 co-resident -> grid barrier deadlock-free).
//   Stage 1: blocks [0,128)   : proj, 16 rows/block
//            blocks [128,256) : impute MLP, 8 rows/block
//   grid barrier
//   Stage 2: all blocks: attn block=(b, 4q, 8 heads) + fused out-GEMM.
// Hot loops use packed fma.rn.f32x2.
// ---------------------------------------------------------------------------
extern __shared__ float as[];
__global__ void __launch_bounds__(256) mega_kernel(
    const float* __restrict__ qv, const float* __restrict__ kv,
    const float* __restrict__ value, const int* __restrict__ mask,
    const float* __restrict__ w1, const float* __restrict__ b1,
    const float* __restrict__ w2,
    const float* __restrict__ wq, const float* __restrict__ bq,
    const float* __restrict__ wk, const float* __restrict__ bk,
    const float* __restrict__ wo, const float* __restrict__ bo,
    const float* __restrict__ imp,
    const float* __restrict__ wd1, const float* __restrict__ bd1,
    const float* __restrict__ lng, const float* __restrict__ lnb,
    const float* __restrict__ wd2, const float* __restrict__ bd2,
    float* __restrict__ y_out, float* __restrict__ qd_out)
{
    int t   = threadIdx.x;
    int blk = blockIdx.x;

    if (blk < 128) {
        // ========== Stage 1a: proj, 16 rows/block ==========
        float* xs_t = as;            // [i][r] 32x16 transposed, 512 f
        float* ht   = as + 512;      // [p][r] 128x16 transposed, 2048 f
        float* et   = as + 2560;     // [p][r] 64x16 transposed, 1024 f
        float* ws2  = as + 3584;     // 8192 f

        int r0 = blk * 16;                     // row in [0,2048)
        bool isQ = r0 < Bn*SQ;
        int rr0 = isQ ? r0 : r0 - Bn*SQ;
        const float* xin = isQ ? qv : kv;
        const float* wp  = isQ ? wq : wk;
        const float* bp  = isQ ? bq : bk;
        float* outp      = isQ ? g_q : g_k;

        // stage w2 (latency hidden by phase 1)
        {
            uint32_t sb = (uint32_t)__cvta_generic_to_shared(ws2);
            #pragma unroll
            for (int j = 0; j < 8; j++) {
                int idx = t + j*256;           // 2048 float4s
                cp_async16(sb + idx*16, w2 + idx*4);
            }
            cp_commit();
        }

        // load 16 input rows, transposed [i][r]
        #pragma unroll
        for (int j = 0; j < 2; j++) {
            int idx = t + j*256;               // 0..511
            int r = idx >> 5, i = idx & 31;
            xs_t[i*16 + r] = xin[rr0*IVD + idx];
        }
        __syncthreads();

        // phase 1: hidden. thread = (col c1 of 128, 8 rows), packed pairs
        {
            int c1  = t & 127;
            int rh1 = (t >> 7) * 8;
            float bb = b1[c1];
            u64 bb2 = pack2(bb, bb);
            u64 a01 = bb2, a23 = bb2, a45 = bb2, a67 = bb2;
            #pragma unroll
            for (int i = 0; i < IVD; i++) {
                float w = w1[i*NH + c1];
                u64 w2p = pack2(w, w);
                ulonglong2 x0 = *(const ulonglong2*)&xs_t[i*16 + rh1];
                ulonglong2 x1 = *(const ulonglong2*)&xs_t[i*16 + rh1 + 4];
                a01 = fma2(x0.x, w2p, a01);
                a23 = fma2(x0.y, w2p, a23);
                a45 = fma2(x1.x, w2p, a45);
                a67 = fma2(x1.y, w2p, a67);
            }
            float v0,v1,v2,v3,v4,v5,v6,v7;
            unpack2(a01, v0, v1); unpack2(a23, v2, v3);
            unpack2(a45, v4, v5); unpack2(a67, v6, v7);
            float4 h0, h1;
            h0.x = fast_tanh(v0); h0.y = fast_tanh(v1);
            h0.z = fast_tanh(v2); h0.w = fast_tanh(v3);
            h1.x = fast_tanh(v4); h1.y = fast_tanh(v5);
            h1.z = fast_tanh(v6); h1.w = fast_tanh(v7);
            *(float4*)&ht[c1*16 + rh1]     = h0;
            *(float4*)&ht[c1*16 + rh1 + 4] = h1;
        }
        cp_wait0();
        __syncthreads();

        int c  = t & 63;
        int rg = (t >> 6) * 4;        // rows rg..rg+3

        // phase 2: embed (all-smem), packed
        {
            u64 a01 = 0, a23 = 0;
            #pragma unroll 8
            for (int p = 0; p < NH; p++) {
                float w = ws2[p*EV + c];
                u64 w2p = pack2(w, w);
                ulonglong2 h = *(const ulonglong2*)&ht[p*16 + rg];
                a01 = fma2(h.x, w2p, a01);
                a23 = fma2(h.y, w2p, a23);
            }
            float o0,o1,o2,o3;
            unpack2(a01, o0, o1); unpack2(a23, o2, o3);
            float4 o; o.x=o0; o.y=o1; o.z=o2; o.w=o3;
            *(float4*)&et[c*16 + rg] = o;
        }
        __syncthreads();

        // phase 3: q/k projection, packed
        {
            float bb = bp[c];
            u64 bb2 = pack2(bb, bb);
            u64 a01 = bb2, a23 = bb2;
            #pragma unroll 8
            for (int p = 0; p < EV; p++) {
                float w = wp[p*EV + c];
                u64 w2p = pack2(w, w);
                ulonglong2 e = *(const ulonglong2*)&et[p*16 + rg];
                a01 = fma2(e.x, w2p, a01);
                a23 = fma2(e.y, w2p, a23);
            }
            float o0,o1,o2,o3;
            unpack2(a01, o0, o1); unpack2(a23, o2, o3);
            outp[(rr0+rg+0)*EV + c] = o0;
            outp[(rr0+rg+1)*EV + c] = o1;
            outp[(rr0+rg+2)*EV + c] = o2;
            outp[(rr0+rg+3)*EV + c] = o3;
        }
    } else {
        // ========== Stage 1b: impute MLP, 8 rows/block ==========
        float* xi   = as;            // [8][16] 128 f
        float* htm  = as + 128;      // [128][8] transposed, 1024 f
        float* redS = as + 1152;     // 32 f
        float* redQ = as + 1184;     // 32 f

        int row0 = (blk - 128) * 8;
        if (t < 128) xi[t] = imp[row0*16 + t];
        __syncthreads();

        int c1   = t & 127;
        int base = (t >> 7) * 4;     // rows base..base+3
        int w8   = t >> 5;
        int lane = t & 31;

        float a[4];
        {
            float bb = bd1[c1];
            #pragma unroll
            for (int j = 0; j < 4; j++) a[j] = bb;
            #pragma unroll
            for (int i = 0; i < 16; i++) {
                float w = wd1[i*NH + c1];
                #pragma unroll
                for (int j = 0; j < 4; j++)
                    a[j] = fmaf(xi[(base+j)*16 + i], w, a[j]);
            }
        }
        float ss[4], qq[4];
        #pragma unroll
        for (int j = 0; j < 4; j++) { ss[j] = a[j]; qq[j] = a[j]*a[j]; }
        #pragma unroll
        for (int off = 16; off > 0; off >>= 1) {
            #pragma unroll
            for (int j = 0; j < 4; j++) {
                ss[j] += __shfl_xor_sync(0xffffffff, ss[j], off);
                qq[j] += __shfl_xor_sync(0xffffffff, qq[j], off);
            }
        }
        if (lane == 0) {
            #pragma unroll
            for (int j = 0; j < 4; j++) { redS[w8*4+j] = ss[j]; redQ[w8*4+j] = qq[j]; }
        }
        __syncthreads();

        float g = lng[c1], be = lnb[c1];
        int gw = (base == 0) ? 0 : 4;
        {
            float4 hv; float* hp = (float*)&hv;
            #pragma unroll
            for (int j = 0; j < 4; j++) {
                float S = redS[(gw+0)*4+j] + redS[(gw+1)*4+j]
                        + redS[(gw+2)*4+j] + redS[(gw+3)*4+j];
                float Q = redQ[(gw+0)*4+j] + redQ[(gw+1)*4+j]
                        + redQ[(gw+2)*4+j] + redQ[(gw+3)*4+j];
                float mu  = S * (1.f/128.f);
                float var = Q * (1.f/128.f) - mu*mu;
                float ln = (a[j] - mu) * rsqrtf(var + 1e-5f) * g + be;
                hp[j] = fmaxf(ln, 0.f);
            }
            *(float4*)&htm[c1*8 + base] = hv;
        }
        __syncthreads();

        // GEMM2, packed row pairs
        {
            float bb = bd2[c1];
            u64 bb2 = pack2(bb, bb);
            u64 a01 = bb2, a23 = bb2;
            #pragma unroll 8
            for (int p = 0; p < NH; p++) {
                float w = wd2[p*NH + c1];
                u64 w2p = pack2(w, w);
                ulonglong2 h = *(const ulonglong2*)&htm[p*8 + base];
                a01 = fma2(h.x, w2p, a01);
                a23 = fma2(h.y, w2p, a23);
            }
            float o0,o1,o2,o3;
            unpack2(a01, o0, o1); unpack2(a23, o2, o3);
            qd_out[(row0+base+0)*NH + c1] = o0;
            qd_out[(row0+base+1)*NH + c1] = o1;
            qd_out[(row0+base+2)*NH + c1] = o2;
            qd_out[(row0+base+3)*NH + c1] = o3;
        }
    }

    // ================= grid barrier =================
    __threadfence();
    __syncthreads();
    if (t == 0) {
        unsigned long long ticket = atomicAdd(&g_bar, 1ULL);
        unsigned long long target = (ticket >> 8) * 256ULL + 256ULL;
        volatile unsigned long long* vb = &g_bar;
        while (*vb < target) { __nanosleep(64); }
        __threadfence();
    }
    __syncthreads();

    // ================= Stage 2: attn + out epilogue =================
    float* ks = as;              // 8192
    float* qs = as + 8192;       // 256
    float* mv = as + 8448;       // 4096
    float* mf = as + 12544;      // 4096
    float* es = as + 16640;      // 4096
    float* xs = mv;              // 1024 overlay after phase B

    int b  = blk >> 5;
    int q0 = (blk & 31) * 4;

    // loads (g_q/g_k via L2 to dodge stale-L1 risk across the barrier)
    {
        const float4* gk4 = (const float4*)g_k;
        float4* ks4 = (float4*)ks;
        #pragma unroll
        for (int j = 0; j < 8; j++) {
            int idx = t + j*256;               // 2048 float4s
            ks4[idx] = __ldcg(&gk4[b*2048 + idx]);
        }
        qs[t] = __ldcg(&g_q[(b*SQ + q0 + (t>>6))*EV + (t&63)]);
        const float4* v4 = (const float4*)(value + b*SK*DIM);
        const int4*   m4 = (const int4*)  (mask  + b*SK*DIM);
        float4* mv4 = (float4*)mv;
        float4* mf4 = (float4*)mf;
        #pragma unroll
        for (int j = 0; j < 4; j++) {
            int idx = t + j*256;               // 1024 float4s
            int4 mm = m4[idx]; float4 vv = v4[idx];
            float4 av, af;
            av.x = mm.x ? vv.x : 0.f;  af.x = mm.x ? 1.f : 0.f;
            av.y = mm.y ? vv.y : 0.f;  af.y = mm.y ? 1.f : 0.f;
            av.z = mm.z ? vv.z : 0.f;  af.z = mm.z ? 1.f : 0.f;
            av.w = mm.w ? vv.w : 0.f;  af.w = mm.w ? 1.f : 0.f;
            mv4[idx] = av; mf4[idx] = af;
        }
    }
    __syncthreads();

    const float scale = 0.35355339059327373f;   // 1/sqrt(8)

    // phase A: scores + softmax weights, packed dot products.
    // vr=(q,h) 0..31, kq 0..7 (16 k each)
    {
        int vr = t >> 3;
        int q = vr >> 3, h = vr & 7;
        int kbase = (t & 7) * 16;
        float4 q0r = *(const float4*)&qs[q*EV + h*DKd];
        float4 q1r = *(const float4*)&qs[q*EV + h*DKd + 4];
        u64 qp0 = pack2(q0r.x, q0r.y);
        u64 qp1 = pack2(q0r.z, q0r.w);
        u64 qp2 = pack2(q1r.x, q1r.y);
        u64 qp3 = pack2(q1r.z, q1r.w);

        float s[16];
        #pragma unroll
        for (int i = 0; i < 16; i++) {
            const ulonglong2* kp = (const ulonglong2*)&ks[(kbase+i)*EV + h*DKd];
            ulonglong2 k0 = kp[0], k1 = kp[1];
            u64 a2 = fma2(qp0, k0.x, 0ULL);
            a2 = fma2(qp1, k0.y, a2);
            a2 = fma2(qp2, k1.x, a2);
            a2 = fma2(qp3, k1.y, a2);
            float lo, hi;
            unpack2(a2, lo, hi);
            s[i] = lo + hi;
        }
        float mx = s[0];
        #pragma unroll
        for (int i = 1; i < 16; i++) mx = fmaxf(mx, s[i]);
        mx = fmaxf(mx, __shfl_xor_sync(0xffffffff, mx, 1));
        mx = fmaxf(mx, __shfl_xor_sync(0xffffffff, mx, 2));
        mx = fmaxf(mx, __shfl_xor_sync(0xffffffff, mx, 4));
        float msc = mx * scale;
        #pragma unroll
        for (int i = 0; i < 16; i++)
            es[vr*SK + kbase + i] = __expf(fmaf(s[i], scale, -msc));
    }
    __syncthreads();

    // phase B: num/den accumulate, packed. vr 0..31, dq 0..7 (4 d each)
    float4 xo;
    int vrB = t >> 3, dqB = t & 7;
    {
        u64 n01 = 0, n23 = 0, d01 = 0, d23 = 0;
        const ulonglong2* mv2 = (const ulonglong2*)mv;
        const ulonglong2* mf2 = (const ulonglong2*)mf;
        const float4* ep4 = (const float4*)&es[vrB*SK];
        #pragma unroll 4
        for (int k4 = 0; k4 < SK/4; k4++) {
            float4 e4 = ep4[k4];
            #pragma unroll
            for (int j = 0; j < 4; j++) {
                float e = (j==0) ? e4.x : (j==1) ? e4.y : (j==2) ? e4.z : e4.w;
                int k = k4*4 + j;
                u64 e2 = pack2(e, e);
                ulonglong2 v = mv2[k*8 + dqB];
                ulonglong2 m = mf2[k*8 + dqB];
                n01 = fma2(e2, v.x, n01);
                n23 = fma2(e2, v.y, n23);
                d01 = fma2(e2, m.x, d01);
                d23 = fma2(e2, m.y, d23);
            }
        }
        float n0,n1,n2,n3, dd0,dd1,dd2,dd3;
        unpack2(n01, n0, n1); unpack2(n23, n2, n3);
        unpack2(d01, dd0, dd1); unpack2(d23, dd2, dd3);
        xo.x = __fdividef(n0, dd0); xo.y = __fdividef(n1, dd1);
        xo.z = __fdividef(n2, dd2); xo.w = __fdividef(n3, dd3);
    }
    __syncthreads();    // mv/mf reads done; safe to overlay xs
    {
        int q = vrB >> 3, h = vrB & 7;
        *(float4*)&xs[q*256 + h*DIM + dqB*4] = xo;
    }
    __syncthreads();

    // epilogue: y[q][c] = sum_p xs[q][p] * wo[p][c] + bo[c]
    // thread = (col pair cp, row qsel); packed col-pair FMA, LDG.64 wo.
    {
        int cp   = (t & 63) * 2;
        int qsel = t >> 6;            // 0..3
        u64 acc = pack2(bo[cp], bo[cp+1]);
        const float* xp = &xs[qsel*256];
        #pragma unroll 8
        for (int p = 0; p < 256; p++) {
            u64 w2p = *(const u64*)&wo[p*NH + cp];
            u64 x2  = pack2(xp[p], xp[p]);
            acc = fma2(x2, w2p, acc);
        }
        float r0v, r1v;
        unpack2(acc, r0v, r1v);
        float2 o; o.x = r0v; o.y = r1v;
        *(float2*)&y_out[(b*SQ + q0 + qsel)*NH + cp] = o;
    }
}

// ---------------------------------------------------------------------------
extern "C" void kernel_launch(void* const* d_in, const int* in_sizes, int n_in,
                              void* d_out, int out_size)
{
    bool dictOrder = (in_sizes[4] == Bn*SK*DIM);

    const float *qv, *kv, *val, *imp, *w1, *b1, *w2, *wq, *bq, *wk, *bk,
                *wo, *bo, *wd1, *bd1, *lng, *lnb, *wd2, *bd2;
    const int* mask;

    if (dictOrder) {
        qv  = (const float*)d_in[0];  kv  = (const float*)d_in[1];
        val = (const float*)d_in[2];  imp = (const float*)d_in[3];
        mask= (const int*)  d_in[4];
        w1  = (const float*)d_in[5];  b1  = (const float*)d_in[6];
        w2  = (const float*)d_in[7];
        wq  = (const float*)d_in[8];  bq  = (const float*)d_in[9];
        wk  = (const float*)d_in[10]; bk  = (const float*)d_in[11];
        wo  = (const float*)d_in[12]; bo  = (const float*)d_in[13];
        wd1 = (const float*)d_in[14]; bd1 = (const float*)d_in[15];
        lng = (const float*)d_in[16]; lnb = (const float*)d_in[17];
        wd2 = (const float*)d_in[18]; bd2 = (const float*)d_in[19];
    } else {
        qv  = (const float*)d_in[0];  kv  = (const float*)d_in[1];
        val = (const float*)d_in[2];  imp = (const float*)d_in[3];
        w1  = (const float*)d_in[4];  b1  = (const float*)d_in[5];
        w2  = (const float*)d_in[6];
        wq  = (const float*)d_in[7];  bq  = (const float*)d_in[8];
        wk  = (const float*)d_in[9];  bk  = (const float*)d_in[10];
        wo  = (const float*)d_in[11]; bo  = (const float*)d_in[12];
        wd1 = (const float*)d_in[13]; bd1 = (const float*)d_in[14];
        lng = (const float*)d_in[15]; lnb = (const float*)d_in[16];
        wd2 = (const float*)d_in[17]; bd2 = (const float*)d_in[18];
        mask= (const int*)  d_in[19];
    }

    float* y  = (float*)d_out;                       // [8,128,128]
    float* qd = (float*)d_out + Bn*SQ*NH;            // [8,128,128]

    cudaFuncSetAttribute(mega_kernel,
                         cudaFuncAttributeMaxDynamicSharedMemorySize,
                         20736 * sizeof(float));

    mega_kernel<<<256, 256, 20736 * sizeof(float)>>>(
        qv, kv, val, mask, w1, b1, w2, wq, bq, wk, bk, wo, bo,
        imp, wd1, bd1, lng, lnb, wd2, bd2, y, qd);
}